// round 15
// baseline (speedup 1.0000x reference)
#include <cuda_runtime.h>

// LengthRegulator, single fused kernel (one graph node):
// block (j,b) computes its own start offset = sum(dur[b,0..j)) with a
// 96-thread strided partial sum + shfl reduce (one barrier), then scatters
// x[b,j,:] into its d frames. Store loop unrolled to 6 predicated slots
// (dataset guarantees d in {2,4,6}); residual loop kept for generality.
// R15 experiment: plain (evict-normal) stores — the 100.7MB output fits in
// the ~126MB L2, so dirty lines may be absorbed instead of streamed to DRAM.

#define BB 32
#define SS 512
#define DD 384
#define T_OUT 2048
#define DV (DD / 4)   // 96 float4 per row

__global__ __launch_bounds__(DV)
void lr_fused_kernel(const float4* __restrict__ x4,
                     const int* __restrict__ dur,
                     float4* __restrict__ out4) {
    __shared__ int part[3];

    const int j = blockIdx.x;
    const int b = blockIdx.y;
    const int t = threadIdx.x;           // 0..95 = float4 channel
    const int w = t >> 5;
    const int lane = t & 31;
    const int idx = b * SS + j;
    const int* dr = dur + b * SS;

    // Issue both long-latency loads first; they overlap the prefix reduce.
    const float4 v = __ldg(&x4[(size_t)idx * DV + t]);
    const int d = __ldg(&dr[j]);

    // ── prologue: start = sum_{p<j} dur[b,p] ────────────────────────────
    int sum = 0;
    for (int p = t; p < j; p += DV)      // <= 6 L2-hit loads per thread
        sum += __ldg(&dr[p]);
    #pragma unroll
    for (int off = 16; off > 0; off >>= 1)
        sum += __shfl_down_sync(0xFFFFFFFFu, sum, off);
    if (lane == 0) part[w] = sum;
    __syncthreads();
    const int start = part[0] + part[1] + part[2];

    // ── copy: 6 predicated stores, evict-normal (L2-absorbable) ─────────
    float4* o = out4 + ((size_t)b * T_OUT + start) * DV + t;
    o[0 * (size_t)DV] = v;
    o[1 * (size_t)DV] = v;
    if (d > 2) {
        o[2 * (size_t)DV] = v;
        o[3 * (size_t)DV] = v;
    }
    if (d > 4) {
        o[4 * (size_t)DV] = v;
        o[5 * (size_t)DV] = v;
    }
    for (int k = 6; k < d; ++k)          // defensive; never taken here
        o[(size_t)k * DV] = v;
}

extern "C" void kernel_launch(void* const* d_in, const int* in_sizes, int n_in,
                              void* d_out, int out_size) {
    const float4* x4  = (const float4*)d_in[0];   // x [B,S,D] f32
    const int*    dur = (const int*)d_in[1];      // durations [B,S] i32
    float4* out4 = (float4*)d_out;                // [B,T_OUT,D] f32

    lr_fused_kernel<<<dim3(SS, BB), DV>>>(x4, dur, out4);
}

// round 16
// speedup vs baseline: 1.2203x; 1.2203x over previous
#include <cuda_runtime.h>

// LengthRegulator — terminal design (champion, R13/R14 family):
// single fused kernel, one graph node. Block (j,b) computes only its own
// start offset = sum(dur[b,0..j)) via a 96-thread strided partial sum +
// shfl reduce (one barrier, ~70 instructions, hidden under the memory wave),
// then scatters x[b,j,:] into its d frames with 6 predicated streaming
// stores (dataset guarantees d in {2,4,6}; residual loop for generality).
// __stcs is load-bearing: evict-normal stores thrash L2 across graph
// replays (+4.4us total, measured R15).

#define BB 32
#define SS 512
#define DD 384
#define T_OUT 2048
#define DV (DD / 4)   // 96 float4 per row

__global__ __launch_bounds__(DV)
void lr_fused_kernel(const float4* __restrict__ x4,
                     const int* __restrict__ dur,
                     float4* __restrict__ out4) {
    __shared__ int part[3];

    const int j = blockIdx.x;
    const int b = blockIdx.y;
    const int t = threadIdx.x;           // 0..95 = float4 channel
    const int w = t >> 5;
    const int lane = t & 31;
    const int idx = b * SS + j;
    const int* dr = dur + b * SS;

    // Issue both long-latency loads first; they overlap the prefix reduce.
    const float4 v = __ldg(&x4[(size_t)idx * DV + t]);
    const int d = __ldg(&dr[j]);

    // ── prologue: start = sum_{p<j} dur[b,p] ────────────────────────────
    int sum = 0;
    for (int p = t; p < j; p += DV)      // <= 6 L2-hit loads per thread
        sum += __ldg(&dr[p]);
    #pragma unroll
    for (int off = 16; off > 0; off >>= 1)
        sum += __shfl_down_sync(0xFFFFFFFFu, sum, off);
    if (lane == 0) part[w] = sum;
    __syncthreads();
    const int start = part[0] + part[1] + part[2];

    // ── copy: 6 predicated streaming stores (d in {2,4,6}) ──────────────
    float4* o = out4 + ((size_t)b * T_OUT + start) * DV + t;
    __stcs(&o[0 * (size_t)DV], v);
    __stcs(&o[1 * (size_t)DV], v);
    if (d > 2) {
        __stcs(&o[2 * (size_t)DV], v);
        __stcs(&o[3 * (size_t)DV], v);
    }
    if (d > 4) {
        __stcs(&o[4 * (size_t)DV], v);
        __stcs(&o[5 * (size_t)DV], v);
    }
    for (int k = 6; k < d; ++k)          // defensive; never taken here
        __stcs(&o[(size_t)k * DV], v);
}

extern "C" void kernel_launch(void* const* d_in, const int* in_sizes, int n_in,
                              void* d_out, int out_size) {
    const float4* x4  = (const float4*)d_in[0];   // x [B,S,D] f32
    const int*    dur = (const int*)d_in[1];      // durations [B,S] i32
    float4* out4 = (float4*)d_out;                // [B,T_OUT,D] f32

    lr_fused_kernel<<<dim3(SS, BB), DV>>>(x4, dur, out4);
}